// round 4
// baseline (speedup 1.0000x reference)
#include <cuda_runtime.h>
#include <cuda_bf16.h>
#include <math.h>

// Problem constants (fixed by the benchmark)
#define NROWS 131072
#define FDIM  256
#define DDIM  256
#define KSLOT 16
#define RDIM  512   // R * D

#define NBLK_A 148
#define NWARP_A (NBLK_A * 8)   // 1184 warps in pass A
#define NPART 16               // reduction partitions (1184 / 16 = 74 warps each)
#define WPP (NWARP_A / NPART)  // 74

// -------- device scratch (static; no runtime allocation allowed) --------
__device__ float g_qk[KSLOT * FDIM];                    // qk[s][f], scale folded in
__device__ float g_scratch[NWARP_A * KSLOT * FDIM];     // per-warp wfeat partials (~18.6 MB)
__device__ float g_scratch_rs[NWARP_A * KSLOT];         // per-warp rowsum partials
__device__ float g_part[NPART * KSLOT * FDIM];          // stage-2 reduction partials

// -------- helpers --------
__device__ __forceinline__ float sigmoidf_(float x) {
    return 1.0f / (1.0f + __expf(-x));
}

// block of 256 threads: mean + rstd of one 256-vector (one value per thread)
__device__ __forceinline__ void block_stats256(float v, float* red, float& mean, float& rstd) {
    float s1 = v, s2 = v * v;
    #pragma unroll
    for (int o = 16; o; o >>= 1) {
        s1 += __shfl_xor_sync(0xffffffffu, s1, o);
        s2 += __shfl_xor_sync(0xffffffffu, s2, o);
    }
    int w = threadIdx.x >> 5;
    if ((threadIdx.x & 31) == 0) { red[w] = s1; red[8 + w] = s2; }
    __syncthreads();
    s1 = 0.f; s2 = 0.f;
    #pragma unroll
    for (int i = 0; i < 8; i++) { s1 += red[i]; s2 += red[8 + i]; }
    mean = s1 * (1.0f / 256.0f);
    float var = s2 * (1.0f / 256.0f) - mean * mean;
    rstd = rsqrtf(var + 1e-5f);
    __syncthreads();   // allow immediate reuse of red
}

// ======================= kernel 1: prep (qk1 from slots_init) =======================
__global__ void k_prep(const float* __restrict__ slots_init,
                       const float* __restrict__ ln_s_g, const float* __restrict__ ln_s_b,
                       const float* __restrict__ Wq, const float* __restrict__ Wk) {
    __shared__ float red[16];
    __shared__ float sv[256];
    __shared__ float qv[256];
    int s = blockIdx.x, t = threadIdx.x;

    float v = slots_init[s * 256 + t];
    float mean, rstd;
    block_stats256(v, red, mean, rstd);
    sv[t] = (v - mean) * rstd * ln_s_g[t] + ln_s_b[t];
    __syncthreads();

    // q[t] = sum_din sv[din] * Wq[din][t]   (Wq is [in,out] row-major -> coalesced)
    float q = 0.f;
    #pragma unroll 4
    for (int d = 0; d < 256; d++) q += sv[d] * Wq[d * 256 + t];
    qv[t] = q;
    __syncthreads();

    // qk[f=t] = sum_d qv[d] * Wk[t][d]   (Wk is [F,D] row-major)
    float qk = 0.f;
    const float* wkr = Wk + t * 256;
    #pragma unroll 4
    for (int d = 0; d < 256; d++) qk += qv[d] * wkr[d];
    g_qk[s * 256 + t] = qk * 0.0625f;   // fold scale = D^-0.5 = 1/16
}

// ======================= kernel 2: pass A (attention + rank-16 accumulation) ==========
__global__ void __launch_bounds__(256, 1)
k_pass_a(const float* __restrict__ features,
         const float* __restrict__ lnf_g, const float* __restrict__ lnf_b) {
    __shared__ float qk_sh[KSLOT * FDIM];
    __shared__ float g_sh[256], b_sh[256];
    int t = threadIdx.x;
    for (int i = t; i < KSLOT * FDIM; i += 256) qk_sh[i] = g_qk[i];
    g_sh[t] = lnf_g[t];
    b_sh[t] = lnf_b[t];
    __syncthreads();

    int lane = t & 31, w = t >> 5;
    int gw = blockIdx.x * 8 + w;

    float acc[128];               // acc[s*8+i]: wfeat partials for f = lane + 32*i
    #pragma unroll
    for (int i = 0; i < 128; i++) acc[i] = 0.f;
    float rsum[16];
    #pragma unroll
    for (int s = 0; s < 16; s++) rsum[s] = 0.f;

    for (int row = gw; row < NROWS; row += NWARP_A) {
        const float* fp = features + (size_t)row * 256 + lane;
        float xv[8];
        float s1 = 0.f, s2 = 0.f;
        #pragma unroll
        for (int i = 0; i < 8; i++) {
            float v = fp[32 * i];
            xv[i] = v; s1 += v; s2 += v * v;
        }
        #pragma unroll
        for (int o = 16; o; o >>= 1) {
            s1 += __shfl_xor_sync(0xffffffffu, s1, o);
            s2 += __shfl_xor_sync(0xffffffffu, s2, o);
        }
        float mean = s1 * (1.0f / 256.0f);
        float rstd = rsqrtf(s2 * (1.0f / 256.0f) - mean * mean + 1e-5f);
        #pragma unroll
        for (int i = 0; i < 8; i++)
            xv[i] = (xv[i] - mean) * rstd * g_sh[lane + 32 * i] + b_sh[lane + 32 * i];

        float p[16];
        #pragma unroll
        for (int s = 0; s < 16; s++) p[s] = 0.f;
        #pragma unroll
        for (int i = 0; i < 8; i++) {
            const float* q = qk_sh + lane + 32 * i;
            #pragma unroll
            for (int s = 0; s < 16; s++) p[s] += q[s * 256] * xv[i];
        }
        #pragma unroll
        for (int o = 16; o; o >>= 1) {
            #pragma unroll
            for (int s = 0; s < 16; s++) p[s] += __shfl_xor_sync(0xffffffffu, p[s], o);
        }
        // softmax over slot axis (identical in all lanes)
        float m = p[0];
        #pragma unroll
        for (int s = 1; s < 16; s++) m = fmaxf(m, p[s]);
        float den = 0.f;
        #pragma unroll
        for (int s = 0; s < 16; s++) { p[s] = __expf(p[s] - m); den += p[s]; }
        float inv = __fdividef(1.0f, den);
        #pragma unroll
        for (int s = 0; s < 16; s++) {
            float a = p[s] * inv;
            rsum[s] += a;
            #pragma unroll
            for (int i = 0; i < 8; i++) acc[s * 8 + i] += a * xv[i];
        }
    }

    // flush per-warp partials (coalesced plain stores, no atomics)
    float* sp = g_scratch + (size_t)gw * (KSLOT * FDIM);
    #pragma unroll
    for (int s = 0; s < 16; s++) {
        #pragma unroll
        for (int i = 0; i < 8; i++)
            sp[s * 256 + lane + 32 * i] = acc[s * 8 + i];
    }
    if (lane == 0) {
        #pragma unroll
        for (int s = 0; s < 16; s++) g_scratch_rs[gw * 16 + s] = rsum[s];
    }
}

// ======================= kernel 3: stage-2 reduction of scratch ======================
__global__ void k_reduce() {
    int s = blockIdx.x & 15;
    int part = blockIdx.x >> 4;
    int t = threadIdx.x;
    const float* sp = g_scratch + s * 256 + t;
    int w0 = part * WPP;
    float a0 = 0.f, a1 = 0.f;
    for (int w = w0; w < w0 + WPP; w += 2) {
        a0 += sp[(size_t)w * 4096];
        a1 += sp[(size_t)(w + 1) * 4096];
    }
    g_part[(part * 16 + s) * 256 + t] = a0 + a1;
}

// ======================= kernel 4: mid (Wv + GRU + MLP + qk2) ========================
__global__ void k_mid(const float* __restrict__ Wv, const float* __restrict__ slots_init,
                      const float* __restrict__ wih, const float* __restrict__ whh,
                      const float* __restrict__ bih, const float* __restrict__ bhh,
                      const float* __restrict__ lnm_g, const float* __restrict__ lnm_b,
                      const float* __restrict__ w1, const float* __restrict__ b1,
                      const float* __restrict__ w2, const float* __restrict__ b2,
                      const float* __restrict__ lns_g, const float* __restrict__ lns_b,
                      const float* __restrict__ Wq, const float* __restrict__ Wk,
                      float* __restrict__ out_slots) {
    __shared__ float red[16];
    __shared__ float shv[256];     // multipurpose: wfeat -> hln -> sln
    __shared__ float sh_upd[256];  // updates -> q
    __shared__ float sh_h[256];
    __shared__ float sh_hid[512];
    int s = blockIdx.x, t = threadIdx.x;

    // finish wfeat reduction: sum 16 partials
    float wf = 0.f;
    #pragma unroll
    for (int p = 0; p < NPART; p++) wf += g_part[(p * 16 + s) * 256 + t];

    // rowsum reduction across 1184 warps
    float rs_p = 0.f;
    for (int w = t; w < NWARP_A; w += 256) rs_p += g_scratch_rs[w * 16 + s];
    #pragma unroll
    for (int o = 16; o; o >>= 1) rs_p += __shfl_xor_sync(0xffffffffu, rs_p, o);
    if ((t & 31) == 0) red[t >> 5] = rs_p;
    __syncthreads();
    float rowsum = 0.f;
    #pragma unroll
    for (int i = 0; i < 8; i++) rowsum += red[i];
    float inv = 1.0f / (rowsum + 1.0f);   // EPSILON = 1.0

    shv[t] = wf;
    __syncthreads();   // also protects red before reuse

    // updates[d=t] = inv * sum_f wfeat[f] * Wv[f][d]
    float upd = 0.f;
    #pragma unroll 4
    for (int f = 0; f < 256; f++) upd += shv[f] * Wv[f * 256 + t];
    upd *= inv;
    sh_upd[t] = upd;
    float h = slots_init[s * 256 + t];
    sh_h[t] = h;
    __syncthreads();

    // GRU gates (order: r, z, n)
    float gi0 = bih[t], gi1 = bih[256 + t], gi2 = bih[512 + t];
    float gh0 = bhh[t], gh1 = bhh[256 + t], gh2 = bhh[512 + t];
    const float* wr0 = wih + (size_t)t * 256;
    const float* wr1 = wih + (size_t)(256 + t) * 256;
    const float* wr2 = wih + (size_t)(512 + t) * 256;
    const float* vr0 = whh + (size_t)t * 256;
    const float* vr1 = whh + (size_t)(256 + t) * 256;
    const float* vr2 = whh + (size_t)(512 + t) * 256;
    #pragma unroll 4
    for (int d = 0; d < 256; d++) {
        float u = sh_upd[d], hh = sh_h[d];
        gi0 += u * wr0[d]; gi1 += u * wr1[d]; gi2 += u * wr2[d];
        gh0 += hh * vr0[d]; gh1 += hh * vr1[d]; gh2 += hh * vr2[d];
    }
    float r = sigmoidf_(gi0 + gh0);
    float z = sigmoidf_(gi1 + gh1);
    float nn = tanhf(gi2 + r * gh2);
    float hnew = (1.0f - z) * nn + z * h;

    // LN_m + MLP residual
    float mean, rstd;
    block_stats256(hnew, red, mean, rstd);
    float hln = (hnew - mean) * rstd * lnm_g[t] + lnm_b[t];
    shv[t] = hln;
    __syncthreads();

    float hid0 = b1[t], hid1 = b1[256 + t];
    #pragma unroll 4
    for (int d = 0; d < 256; d++) {
        float x = shv[d];
        hid0 += x * w1[d * 512 + t];
        hid1 += x * w1[d * 512 + 256 + t];
    }
    sh_hid[t] = fmaxf(hid0, 0.f);
    sh_hid[256 + t] = fmaxf(hid1, 0.f);
    __syncthreads();

    float o = b2[t];
    #pragma unroll 4
    for (int r2 = 0; r2 < 512; r2++) o += sh_hid[r2] * w2[r2 * 256 + t];
    float sf = hnew + o;
    out_slots[s * 256 + t] = sf;   // final slots (straight-through is identity in forward)

    // qk2 for final attention: LN_s(sf) @ Wq @ Wk.T * scale
    block_stats256(sf, red, mean, rstd);
    float sln = (sf - mean) * rstd * lns_g[t] + lns_b[t];
    shv[t] = sln;
    __syncthreads();
    float q = 0.f;
    #pragma unroll 4
    for (int d = 0; d < 256; d++) q += shv[d] * Wq[d * 256 + t];
    sh_upd[t] = q;
    __syncthreads();
    float qk = 0.f;
    const float* wkr = Wk + (size_t)t * 256;
    #pragma unroll 4
    for (int d = 0; d < 256; d++) qk += sh_upd[d] * wkr[d];
    g_qk[s * 256 + t] = qk * 0.0625f;
}

// ======================= kernel 5: pass D (final attention, write attn.T) ============
__global__ void __launch_bounds__(256)
k_pass_d(const float* __restrict__ features,
         const float* __restrict__ lnf_g, const float* __restrict__ lnf_b,
         float* __restrict__ out_attn) {
    __shared__ float qk_sh[KSLOT * FDIM];
    __shared__ float g_sh[256], b_sh[256];
    int t = threadIdx.x;
    for (int i = t; i < KSLOT * FDIM; i += 256) qk_sh[i] = g_qk[i];
    g_sh[t] = lnf_g[t];
    b_sh[t] = lnf_b[t];
    __syncthreads();

    int lane = t & 31, w = t >> 5;
    int gw = blockIdx.x * 8 + w;
    int nw = gridDim.x * 8;

    for (int row = gw; row < NROWS; row += nw) {
        const float* fp = features + (size_t)row * 256 + lane;
        float xv[8];
        float s1 = 0.f, s2 = 0.f;
        #pragma unroll
        for (int i = 0; i < 8; i++) {
            float v = fp[32 * i];
            xv[i] = v; s1 += v; s2 += v * v;
        }
        #pragma unroll
        for (int o = 16; o; o >>= 1) {
            s1 += __shfl_xor_sync(0xffffffffu, s1, o);
            s2 += __shfl_xor_sync(0xffffffffu, s2, o);
        }
        float mean = s1 * (1.0f / 256.0f);
        float rstd = rsqrtf(s2 * (1.0f / 256.0f) - mean * mean + 1e-5f);
        #pragma unroll
        for (int i = 0; i < 8; i++)
            xv[i] = (xv[i] - mean) * rstd * g_sh[lane + 32 * i] + b_sh[lane + 32 * i];

        float p[16];
        #pragma unroll
        for (int s = 0; s < 16; s++) p[s] = 0.f;
        #pragma unroll
        for (int i = 0; i < 8; i++) {
            const float* q = qk_sh + lane + 32 * i;
            #pragma unroll
            for (int s = 0; s < 16; s++) p[s] += q[s * 256] * xv[i];
        }
        #pragma unroll
        for (int o = 16; o; o >>= 1) {
            #pragma unroll
            for (int s = 0; s < 16; s++) p[s] += __shfl_xor_sync(0xffffffffu, p[s], o);
        }
        float m = p[0];
        #pragma unroll
        for (int s = 1; s < 16; s++) m = fmaxf(m, p[s]);
        float den = 0.f;
        #pragma unroll
        for (int s = 0; s < 16; s++) { p[s] = __expf(p[s] - m); den += p[s]; }
        float inv = __fdividef(1.0f, den);

        // lane l (<16) writes attn.T[row][l]
        float out_v = p[0];
        #pragma unroll
        for (int s = 1; s < 16; s++) if (lane == s) out_v = p[s];
        if (lane < 16) out_attn[(size_t)row * 16 + lane] = out_v * inv;
    }
}

// ======================= launcher =======================
extern "C" void kernel_launch(void* const* d_in, const int* in_sizes, int n_in,
                              void* d_out, int out_size) {
    const float* features  = (const float*)d_in[0];
    const float* ln_f_g    = (const float*)d_in[1];
    const float* ln_f_b    = (const float*)d_in[2];
    const float* ln_s_g    = (const float*)d_in[3];
    const float* ln_s_b    = (const float*)d_in[4];
    const float* ln_m_g    = (const float*)d_in[5];
    const float* ln_m_b    = (const float*)d_in[6];
    const float* Wq        = (const float*)d_in[7];
    const float* Wk        = (const float*)d_in[8];
    const float* Wv        = (const float*)d_in[9];
    const float* gru_wih   = (const float*)d_in[10];
    const float* gru_whh   = (const float*)d_in[11];
    const float* gru_bih   = (const float*)d_in[12];
    const float* gru_bhh   = (const float*)d_in[13];
    const float* mlp_w1    = (const float*)d_in[14];
    const float* mlp_b1    = (const float*)d_in[15];
    const float* mlp_w2    = (const float*)d_in[16];
    const float* mlp_b2    = (const float*)d_in[17];
    const float* slots_init= (const float*)d_in[18];
    // d_in[19] = num_iter (fixed at 2 -> exactly one update iteration)

    float* out = (float*)d_out;                 // [0:4096) slots, [4096:) attn [N,16]

    k_prep<<<KSLOT, 256>>>(slots_init, ln_s_g, ln_s_b, Wq, Wk);
    k_pass_a<<<NBLK_A, 256>>>(features, ln_f_g, ln_f_b);
    k_reduce<<<NPART * KSLOT, 256>>>();
    k_mid<<<KSLOT, 256>>>(Wv, slots_init, gru_wih, gru_whh, gru_bih, gru_bhh,
                          ln_m_g, ln_m_b, mlp_w1, mlp_b1, mlp_w2, mlp_b2,
                          ln_s_g, ln_s_b, Wq, Wk, out);
    k_pass_d<<<592, 256>>>(features, ln_f_g, ln_f_b, out + KSLOT * DDIM);
}

// round 5
// speedup vs baseline: 2.3307x; 2.3307x over previous
#include <cuda_runtime.h>
#include <math.h>

typedef unsigned long long ull;

// Problem constants
#define NROWS 131072
#define KSLOT 16
#define NBLK_A 148
#define NWARP_A (NBLK_A * 8)      // 1184
#define NPART 16
#define WPP (NWARP_A / NPART)     // 74

// -------- device scratch (static) --------
__device__ float g_qk[KSLOT * 256];                 // qk[s][f], scale folded
__device__ float g_qT[256 * KSLOT];                 // q transposed [d][s]
__device__ float g_scratch[NWARP_A * KSLOT * 256];  // per-warp wfeat partials
__device__ float g_scratch_rs[NWARP_A * KSLOT];
__device__ float g_part[NPART * KSLOT * 256];
__device__ float g_upd[KSLOT * 256];
__device__ float g_gi[768 * KSLOT];                 // gi[j][s]
__device__ float g_gh[768 * KSLOT];
__device__ float g_hnew[KSLOT * 256];
__device__ float g_hln[KSLOT * 256];
__device__ float g_hid[KSLOT * 512];

// -------- f32x2 packed helpers --------
#define FMA2(d,a,b,c) asm("fma.rn.f32x2 %0, %1, %2, %3;" : "=l"(d) : "l"(a), "l"(b), "l"(c))
#define PACK2(d,lo,hi) asm("mov.b64 %0, {%1, %2};" : "=l"(d) : "r"(__float_as_uint(lo)), "r"(__float_as_uint(hi)))
#define UNPK2(lo,hi,src) do { unsigned _ul,_uh; \
    asm("mov.b64 {%0, %1}, %2;" : "=r"(_ul), "=r"(_uh) : "l"(src)); \
    lo = __uint_as_float(_ul); hi = __uint_as_float(_uh); } while(0)

// -------- warp helpers --------
// reduce-scatter 16 values across 32 lanes; returns sum for s=(lane>>1)&15
__device__ __forceinline__ float rs16(const float* v, int lane) {
    bool b4 = (lane & 16) != 0, b3 = (lane & 8) != 0, bb2 = (lane & 4) != 0, bb1 = (lane & 2) != 0;
    float w[8];
    #pragma unroll
    for (int i = 0; i < 8; i++) {
        float snd = b4 ? v[i] : v[i + 8];
        float kp  = b4 ? v[i + 8] : v[i];
        w[i] = kp + __shfl_xor_sync(0xffffffffu, snd, 16);
    }
    float u[4];
    #pragma unroll
    for (int i = 0; i < 4; i++) {
        float snd = b3 ? w[i] : w[i + 4];
        float kp  = b3 ? w[i + 4] : w[i];
        u[i] = kp + __shfl_xor_sync(0xffffffffu, snd, 8);
    }
    float x[2];
    #pragma unroll
    for (int i = 0; i < 2; i++) {
        float snd = bb2 ? u[i] : u[i + 2];
        float kp  = bb2 ? u[i + 2] : u[i];
        x[i] = kp + __shfl_xor_sync(0xffffffffu, snd, 4);
    }
    float snd = bb1 ? x[0] : x[1];
    float kp  = bb1 ? x[1] : x[0];
    float r = kp + __shfl_xor_sync(0xffffffffu, snd, 2);
    r += __shfl_xor_sync(0xffffffffu, r, 1);
    return r;
}

// softmax over the 16 distributed values (each present twice across 32 lanes)
__device__ __forceinline__ float softmax16(float r) {
    float m = r;
    #pragma unroll
    for (int o = 16; o; o >>= 1) m = fmaxf(m, __shfl_xor_sync(0xffffffffu, m, o));
    float e = __expf(r - m);
    float d = e;
    #pragma unroll
    for (int o = 16; o; o >>= 1) d += __shfl_xor_sync(0xffffffffu, d, o);
    return e * __fdividef(2.0f, d);   // each value counted twice
}

// block of 256 threads: mean + rstd of one 256-vector
__device__ __forceinline__ void block_stats256(float v, float* red, float& mean, float& rstd) {
    float s1 = v, s2 = v * v;
    #pragma unroll
    for (int o = 16; o; o >>= 1) {
        s1 += __shfl_xor_sync(0xffffffffu, s1, o);
        s2 += __shfl_xor_sync(0xffffffffu, s2, o);
    }
    int w = threadIdx.x >> 5;
    if ((threadIdx.x & 31) == 0) { red[w] = s1; red[8 + w] = s2; }
    __syncthreads();
    s1 = 0.f; s2 = 0.f;
    #pragma unroll
    for (int i = 0; i < 8; i++) { s1 += red[i]; s2 += red[8 + i]; }
    mean = s1 * (1.0f / 256.0f);
    float var = s2 * (1.0f / 256.0f) - mean * mean;
    rstd = rsqrtf(var + 1e-5f);
    __syncthreads();
}

// ================= k_prep: LN(slots_init) @ Wq -> g_qT =================
__global__ void k_prep(const float* __restrict__ slots_init,
                       const float* __restrict__ ln_s_g, const float* __restrict__ ln_s_b,
                       const float* __restrict__ Wq) {
    __shared__ float red[16];
    __shared__ float sv[256];
    int s = blockIdx.x, t = threadIdx.x;
    float v = slots_init[s * 256 + t];
    float mean, rstd;
    block_stats256(v, red, mean, rstd);
    sv[t] = (v - mean) * rstd * ln_s_g[t] + ln_s_b[t];
    __syncthreads();
    float a0 = 0.f, a1 = 0.f, a2 = 0.f, a3 = 0.f;
    #pragma unroll 4
    for (int d = 0; d < 256; d += 4) {
        a0 += sv[d] * Wq[d * 256 + t];
        a1 += sv[d + 1] * Wq[(d + 1) * 256 + t];
        a2 += sv[d + 2] * Wq[(d + 2) * 256 + t];
        a3 += sv[d + 3] * Wq[(d + 3) * 256 + t];
    }
    g_qT[t * 16 + s] = (a0 + a1) + (a2 + a3);
}

// ================= k_qk: qk[s][f] = q[s] . Wk[f]  (warp per f, broadcast) ========
__global__ void k_qk(const float* __restrict__ Wk) {
    __shared__ float qT[4096];
    int t = threadIdx.x;
    for (int idx = t; idx < 4096; idx += 256) qT[idx] = g_qT[idx];
    __syncthreads();
    int lane = t & 31, w = t >> 5;
    int f = blockIdx.x * 8 + w;
    int c = lane >> 4, s = lane & 15;
    const float* wk = Wk + f * 256 + c;
    float a = 0.f;
    #pragma unroll 8
    for (int i = 0; i < 128; i++)
        a += qT[(2 * i + c) * 16 + s] * wk[2 * i];
    a += __shfl_xor_sync(0xffffffffu, a, 16);
    if (lane < 16) g_qk[lane * 256 + f] = a * 0.0625f;   // scale = D^-0.5
}

// ================= pass A: fused LN + logits + softmax + rank-16 accum ===========
__global__ void __launch_bounds__(256, 1)
k_pass_a(const float* __restrict__ features,
         const float* __restrict__ lnf_g, const float* __restrict__ lnf_b) {
    __shared__ ull qk2[2048];     // [s][i2][lane] packed pairs {f, f+32}
    __shared__ ull g2s[128], b2s[128];
    int t = threadIdx.x;
    for (int idx = t; idx < 2048; idx += 256) {
        int s = idx >> 7, r = idx & 127, i2 = r >> 5, ln = r & 31;
        ull v; PACK2(v, g_qk[s * 256 + 64 * i2 + ln], g_qk[s * 256 + 64 * i2 + 32 + ln]);
        qk2[idx] = v;
    }
    if (t < 128) {
        int i2 = t >> 5, ln = t & 31;
        ull v;
        PACK2(v, lnf_g[64 * i2 + ln], lnf_g[64 * i2 + 32 + ln]); g2s[t] = v;
        PACK2(v, lnf_b[64 * i2 + ln], lnf_b[64 * i2 + 32 + ln]); b2s[t] = v;
    }
    __syncthreads();

    int lane = t & 31, w = t >> 5;
    int gw = blockIdx.x * 8 + w;

    ull acc2[64];
    #pragma unroll
    for (int i = 0; i < 64; i++) acc2[i] = 0ull;
    float rsum = 0.f;

    for (int pi = gw; pi < NROWS / 2; pi += NWARP_A) {
        const float* fp0 = features + (size_t)(2 * pi) * 256 + lane;
        const float* fp1 = fp0 + 256;
        float xv0[8], xv1[8];
        #pragma unroll
        for (int i = 0; i < 8; i++) { xv0[i] = fp0[32 * i]; xv1[i] = fp1[32 * i]; }
        float s10 = 0.f, s20 = 0.f, s11 = 0.f, s21 = 0.f;
        #pragma unroll
        for (int i = 0; i < 8; i++) {
            s10 += xv0[i]; s20 += xv0[i] * xv0[i];
            s11 += xv1[i]; s21 += xv1[i] * xv1[i];
        }
        #pragma unroll
        for (int o = 16; o; o >>= 1) {
            s10 += __shfl_xor_sync(0xffffffffu, s10, o);
            s20 += __shfl_xor_sync(0xffffffffu, s20, o);
            s11 += __shfl_xor_sync(0xffffffffu, s11, o);
            s21 += __shfl_xor_sync(0xffffffffu, s21, o);
        }
        float m0 = s10 * (1.f / 256), m1 = s11 * (1.f / 256);
        float r0 = rsqrtf(s20 * (1.f / 256) - m0 * m0 + 1e-5f);
        float r1 = rsqrtf(s21 * (1.f / 256) - m1 * m1 + 1e-5f);
        ull rr0, nm0, rr1, nm1;
        PACK2(rr0, r0, r0); float n0 = -m0 * r0; PACK2(nm0, n0, n0);
        PACK2(rr1, r1, r1); float n1 = -m1 * r1; PACK2(nm1, n1, n1);
        ull xp0[4], xp1[4];
        #pragma unroll
        for (int i2 = 0; i2 < 4; i2++) {
            ull xr, tz;
            PACK2(xr, xv0[2 * i2], xv0[2 * i2 + 1]);
            FMA2(tz, xr, rr0, nm0);
            FMA2(xp0[i2], tz, g2s[i2 * 32 + lane], b2s[i2 * 32 + lane]);
            PACK2(xr, xv1[2 * i2], xv1[2 * i2 + 1]);
            FMA2(tz, xr, rr1, nm1);
            FMA2(xp1[i2], tz, g2s[i2 * 32 + lane], b2s[i2 * 32 + lane]);
        }
        float p0[16], p1[16];
        #pragma unroll
        for (int s = 0; s < 16; s++) {
            ull t0 = 0ull, t1 = 0ull;
            #pragma unroll
            for (int i2 = 0; i2 < 4; i2++) {
                ull q = qk2[(s * 4 + i2) * 32 + lane];
                FMA2(t0, q, xp0[i2], t0);
                FMA2(t1, q, xp1[i2], t1);
            }
            float lo, hi;
            UNPK2(lo, hi, t0); p0[s] = lo + hi;
            UNPK2(lo, hi, t1); p1[s] = lo + hi;
        }
        float a0 = softmax16(rs16(p0, lane));
        float a1 = softmax16(rs16(p1, lane));
        rsum += a0 + a1;
        #pragma unroll
        for (int s = 0; s < 16; s++) {
            float av0 = __shfl_sync(0xffffffffu, a0, 2 * s);
            float av1 = __shfl_sync(0xffffffffu, a1, 2 * s);
            ull A0, A1; PACK2(A0, av0, av0); PACK2(A1, av1, av1);
            #pragma unroll
            for (int i2 = 0; i2 < 4; i2++) {
                FMA2(acc2[s * 4 + i2], A0, xp0[i2], acc2[s * 4 + i2]);
                FMA2(acc2[s * 4 + i2], A1, xp1[i2], acc2[s * 4 + i2]);
            }
        }
    }

    float* sp = g_scratch + (size_t)gw * 4096;
    #pragma unroll
    for (int s = 0; s < 16; s++) {
        #pragma unroll
        for (int i2 = 0; i2 < 4; i2++) {
            float lo, hi; UNPK2(lo, hi, acc2[s * 4 + i2]);
            sp[s * 256 + 64 * i2 + lane] = lo;
            sp[s * 256 + 64 * i2 + 32 + lane] = hi;
        }
    }
    if (!(lane & 1)) g_scratch_rs[gw * 16 + (lane >> 1)] = rsum;
}

// ================= k_reduce: stage-2 reduction of scratch =================
__global__ void k_reduce() {
    int s = blockIdx.x & 15;
    int part = blockIdx.x >> 4;
    int t = threadIdx.x;
    const float* sp = g_scratch + s * 256 + t;
    int w0 = part * WPP;
    float a0 = 0.f, a1 = 0.f;
    for (int w = w0; w < w0 + WPP; w += 2) {
        a0 += sp[(size_t)w * 4096];
        a1 += sp[(size_t)(w + 1) * 4096];
    }
    g_part[(part * 16 + s) * 256 + t] = a0 + a1;
}

// ================= k_upd: finish reduction + Wv GEMV (coalesced) ============
__global__ void k_upd(const float* __restrict__ Wv) {
    __shared__ float red[16];
    __shared__ float shv[256];
    int s = blockIdx.x, t = threadIdx.x;
    float wf = 0.f;
    #pragma unroll
    for (int p = 0; p < NPART; p++) wf += g_part[(p * 16 + s) * 256 + t];
    float rs_p = 0.f;
    for (int w = t; w < NWARP_A; w += 256) rs_p += g_scratch_rs[w * 16 + s];
    #pragma unroll
    for (int o = 16; o; o >>= 1) rs_p += __shfl_xor_sync(0xffffffffu, rs_p, o);
    if ((t & 31) == 0) red[t >> 5] = rs_p;
    shv[t] = wf;
    __syncthreads();
    float rowsum = 0.f;
    #pragma unroll
    for (int i = 0; i < 8; i++) rowsum += red[i];
    float inv = 1.0f / (rowsum + 1.0f);   // EPSILON = 1.0
    float a0 = 0.f, a1 = 0.f, a2 = 0.f, a3 = 0.f;
    #pragma unroll 4
    for (int f = 0; f < 256; f += 4) {
        a0 += shv[f] * Wv[f * 256 + t];
        a1 += shv[f + 1] * Wv[(f + 1) * 256 + t];
        a2 += shv[f + 2] * Wv[(f + 2) * 256 + t];
        a3 += shv[f + 3] * Wv[(f + 3) * 256 + t];
    }
    g_upd[s * 256 + t] = ((a0 + a1) + (a2 + a3)) * inv;
}

// ================= k_gates: GRU gi/gh, warp per output j (768 warps) ============
__global__ void k_gates(const float* __restrict__ wih, const float* __restrict__ whh,
                        const float* __restrict__ slots_init) {
    __shared__ float upd_t[4096];   // [d][s]
    __shared__ float h_t[4096];
    int t = threadIdx.x;
    for (int idx = t; idx < 4096; idx += 256) {
        int s = idx >> 8, d = idx & 255;
        upd_t[d * 16 + s] = g_upd[idx];
        h_t[d * 16 + s] = slots_init[idx];
    }
    __syncthreads();
    int lane = t & 31, w = t >> 5;
    int j = blockIdx.x * 8 + w;
    int c = lane >> 4, s = lane & 15;
    const float* wi = wih + (size_t)j * 256 + c;
    const float* wh = whh + (size_t)j * 256 + c;
    float ai = 0.f, ah = 0.f;
    #pragma unroll 8
    for (int i = 0; i < 128; i++) {
        int d = 2 * i + c;
        ai += upd_t[d * 16 + s] * wi[2 * i];
        ah += h_t[d * 16 + s] * wh[2 * i];
    }
    ai += __shfl_xor_sync(0xffffffffu, ai, 16);
    ah += __shfl_xor_sync(0xffffffffu, ah, 16);
    if (lane < 16) {
        g_gi[j * 16 + lane] = ai;
        g_gh[j * 16 + lane] = ah;
    }
}

// ================= k_point: GRU pointwise + LN_m =================
__global__ void k_point(const float* __restrict__ slots_init,
                        const float* __restrict__ bih, const float* __restrict__ bhh,
                        const float* __restrict__ lnm_g, const float* __restrict__ lnm_b) {
    __shared__ float red[16];
    int s = blockIdx.x, t = threadIdx.x;
    float gi0 = g_gi[t * 16 + s] + bih[t];
    float gi1 = g_gi[(256 + t) * 16 + s] + bih[256 + t];
    float gi2 = g_gi[(512 + t) * 16 + s] + bih[512 + t];
    float gh0 = g_gh[t * 16 + s] + bhh[t];
    float gh1 = g_gh[(256 + t) * 16 + s] + bhh[256 + t];
    float gh2 = g_gh[(512 + t) * 16 + s] + bhh[512 + t];
    float h = slots_init[s * 256 + t];
    float r = 1.0f / (1.0f + __expf(-(gi0 + gh0)));
    float z = 1.0f / (1.0f + __expf(-(gi1 + gh1)));
    float nn = tanhf(gi2 + r * gh2);
    float hnew = (1.0f - z) * nn + z * h;
    float mean, rstd;
    block_stats256(hnew, red, mean, rstd);
    g_hnew[s * 256 + t] = hnew;
    g_hln[s * 256 + t] = (hnew - mean) * rstd * lnm_g[t] + lnm_b[t];
}

// ================= k_mlp1: hid = relu(hln @ w1 + b1) (coalesced) =================
__global__ void k_mlp1(const float* __restrict__ w1, const float* __restrict__ b1) {
    __shared__ float hl[256];
    int s = blockIdx.x, t = threadIdx.x;
    if (t < 256) hl[t] = g_hln[s * 256 + t];
    __syncthreads();
    float a0 = b1[t], a1 = 0.f, a2 = 0.f, a3 = 0.f;
    #pragma unroll 4
    for (int d = 0; d < 256; d += 4) {
        a0 += hl[d] * w1[d * 512 + t];
        a1 += hl[d + 1] * w1[(d + 1) * 512 + t];
        a2 += hl[d + 2] * w1[(d + 2) * 512 + t];
        a3 += hl[d + 3] * w1[(d + 3) * 512 + t];
    }
    g_hid[s * 512 + t] = fmaxf((a0 + a1) + (a2 + a3), 0.f);
}

// ============ k_mlp2: out = hnew + hid@w2+b2; write slots; LN_s; q -> g_qT ========
__global__ void k_mlp2(const float* __restrict__ w2, const float* __restrict__ b2p,
                       const float* __restrict__ lns_g, const float* __restrict__ lns_b,
                       const float* __restrict__ Wq, float* __restrict__ out_slots) {
    __shared__ float hid[512];
    __shared__ float red[16];
    __shared__ float sv[256];
    int s = blockIdx.x, t = threadIdx.x;
    hid[t] = g_hid[s * 512 + t];
    hid[256 + t] = g_hid[s * 512 + 256 + t];
    __syncthreads();
    float a0 = b2p[t], a1 = 0.f, a2 = 0.f, a3 = 0.f;
    #pragma unroll 4
    for (int r = 0; r < 512; r += 4) {
        a0 += hid[r] * w2[r * 256 + t];
        a1 += hid[r + 1] * w2[(r + 1) * 256 + t];
        a2 += hid[r + 2] * w2[(r + 2) * 256 + t];
        a3 += hid[r + 3] * w2[(r + 3) * 256 + t];
    }
    float sf = g_hnew[s * 256 + t] + ((a0 + a1) + (a2 + a3));
    out_slots[s * 256 + t] = sf;
    float mean, rstd;
    block_stats256(sf, red, mean, rstd);
    sv[t] = (sf - mean) * rstd * lns_g[t] + lns_b[t];
    __syncthreads();
    float q0 = 0.f, q1 = 0.f, q2 = 0.f, q3 = 0.f;
    #pragma unroll 4
    for (int d = 0; d < 256; d += 4) {
        q0 += sv[d] * Wq[d * 256 + t];
        q1 += sv[d + 1] * Wq[(d + 1) * 256 + t];
        q2 += sv[d + 2] * Wq[(d + 2) * 256 + t];
        q3 += sv[d + 3] * Wq[(d + 3) * 256 + t];
    }
    g_qT[t * 16 + s] = (q0 + q1) + (q2 + q3);
}

// ================= pass D: final attention, write attn.T [N,16] =================
__global__ void __launch_bounds__(256)
k_pass_d(const float* __restrict__ features,
         const float* __restrict__ lnf_g, const float* __restrict__ lnf_b,
         float* __restrict__ out_attn) {
    __shared__ ull qk2[2048];
    __shared__ ull g2s[128], b2s[128];
    int t = threadIdx.x;
    for (int idx = t; idx < 2048; idx += 256) {
        int s = idx >> 7, r = idx & 127, i2 = r >> 5, ln = r & 31;
        ull v; PACK2(v, g_qk[s * 256 + 64 * i2 + ln], g_qk[s * 256 + 64 * i2 + 32 + ln]);
        qk2[idx] = v;
    }
    if (t < 128) {
        int i2 = t >> 5, ln = t & 31;
        ull v;
        PACK2(v, lnf_g[64 * i2 + ln], lnf_g[64 * i2 + 32 + ln]); g2s[t] = v;
        PACK2(v, lnf_b[64 * i2 + ln], lnf_b[64 * i2 + 32 + ln]); b2s[t] = v;
    }
    __syncthreads();

    int lane = t & 31, w = t >> 5;
    int gw = blockIdx.x * 8 + w;
    int nw = gridDim.x * 8;

    for (int pi = gw; pi < NROWS / 2; pi += nw) {
        const float* fp0 = features + (size_t)(2 * pi) * 256 + lane;
        const float* fp1 = fp0 + 256;
        float xv0[8], xv1[8];
        #pragma unroll
        for (int i = 0; i < 8; i++) { xv0[i] = fp0[32 * i]; xv1[i] = fp1[32 * i]; }
        float s10 = 0.f, s20 = 0.f, s11 = 0.f, s21 = 0.f;
        #pragma unroll
        for (int i = 0; i < 8; i++) {
            s10 += xv0[i]; s20 += xv0[i] * xv0[i];
            s11 += xv1[i]; s21 += xv1[i] * xv1[i];
        }
        #pragma unroll
        for (int o = 16; o; o >>= 1) {
            s10 += __shfl_xor_sync(0xffffffffu, s10, o);
            s20 += __shfl_xor_sync(0xffffffffu, s20, o);
            s11 += __shfl_xor_sync(0xffffffffu, s11, o);
            s21 += __shfl_xor_sync(0xffffffffu, s21, o);
        }
        float m0 = s10 * (1.f / 256), m1 = s11 * (1.f / 256);
        float r0 = rsqrtf(s20 * (1.f / 256) - m0 * m0 + 1e-5f);
        float r1 = rsqrtf(s21 * (1.f / 256) - m1 * m1 + 1e-5f);
        ull rr0, nm0, rr1, nm1;
        PACK2(rr0, r0, r0); float n0 = -m0 * r0; PACK2(nm0, n0, n0);
        PACK2(rr1, r1, r1); float n1 = -m1 * r1; PACK2(nm1, n1, n1);
        ull xp0[4], xp1[4];
        #pragma unroll
        for (int i2 = 0; i2 < 4; i2++) {
            ull xr, tz;
            PACK2(xr, xv0[2 * i2], xv0[2 * i2 + 1]);
            FMA2(tz, xr, rr0, nm0);
            FMA2(xp0[i2], tz, g2s[i2 * 32 + lane], b2s[i2 * 32 + lane]);
            PACK2(xr, xv1[2 * i2], xv1[2 * i2 + 1]);
            FMA2(tz, xr, rr1, nm1);
            FMA2(xp1[i2], tz, g2s[i2 * 32 + lane], b2s[i2 * 32 + lane]);
        }
        float p0[16], p1[16];
        #pragma unroll
        for (int s = 0; s < 16; s++) {
            ull t0 = 0ull, t1 = 0ull;
            #pragma unroll
            for (int i2 = 0; i2 < 4; i2++) {
                ull q = qk2[(s * 4 + i2) * 32 + lane];
                FMA2(t0, q, xp0[i2], t0);
                FMA2(t1, q, xp1[i2], t1);
            }
            float lo, hi;
            UNPK2(lo, hi, t0); p0[s] = lo + hi;
            UNPK2(lo, hi, t1); p1[s] = lo + hi;
        }
        float a0 = softmax16(rs16(p0, lane));
        float a1 = softmax16(rs16(p1, lane));
        if (!(lane & 1)) {
            int s = lane >> 1;
            out_attn[(size_t)(2 * pi) * 16 + s] = a0;
            out_attn[(size_t)(2 * pi + 1) * 16 + s] = a1;
        }
    }
}

// ================= launcher =================
extern "C" void kernel_launch(void* const* d_in, const int* in_sizes, int n_in,
                              void* d_out, int out_size) {
    const float* features   = (const float*)d_in[0];
    const float* ln_f_g     = (const float*)d_in[1];
    const float* ln_f_b     = (const float*)d_in[2];
    const float* ln_s_g     = (const float*)d_in[3];
    const float* ln_s_b     = (const float*)d_in[4];
    const float* ln_m_g     = (const float*)d_in[5];
    const float* ln_m_b     = (const float*)d_in[6];
    const float* Wq         = (const float*)d_in[7];
    const float* Wk         = (const float*)d_in[8];
    const float* Wv         = (const float*)d_in[9];
    const float* gru_wih    = (const float*)d_in[10];
    const float* gru_whh    = (const float*)d_in[11];
    const float* gru_bih    = (const float*)d_in[12];
    const float* gru_bhh    = (const float*)d_in[13];
    const float* mlp_w1     = (const float*)d_in[14];
    const float* mlp_b1     = (const float*)d_in[15];
    const float* mlp_w2     = (const float*)d_in[16];
    const float* mlp_b2     = (const float*)d_in[17];
    const float* slots_init = (const float*)d_in[18];
    // d_in[19] = num_iter (fixed at 2 -> exactly one update iteration)

    float* out = (float*)d_out;   // [0:4096) slots, [4096:) attn [N,16]

    k_prep<<<KSLOT, 256>>>(slots_init, ln_s_g, ln_s_b, Wq);
    k_qk<<<32, 256>>>(Wk);
    k_pass_a<<<NBLK_A, 256>>>(features, ln_f_g, ln_f_b);
    k_reduce<<<NPART * KSLOT, 256>>>();
    k_upd<<<KSLOT, 256>>>(Wv);
    k_gates<<<96, 256>>>(gru_wih, gru_whh, slots_init);
    k_point<<<KSLOT, 256>>>(slots_init, gru_bih, gru_bhh, ln_m_g, ln_m_b);
    k_mlp1<<<KSLOT, 512>>>(mlp_w1, mlp_b1);
    k_mlp2<<<KSLOT, 256>>>(mlp_w2, mlp_b2, ln_s_g, ln_s_b, Wq, out);
    k_qk<<<32, 256>>>(Wk);
    k_pass_d<<<592, 256>>>(features, ln_f_g, ln_f_b, out + KSLOT * 256);
}